// round 10
// baseline (speedup 1.0000x reference)
#include <cuda_runtime.h>
#include <cstdint>

#define N_USERS 100000
#define N_ITEMS 200000
#define N_NODES (N_USERS + N_ITEMS)
#define EMB 64
#define N_HOPS 3
#define NNZ 2000000
#define CAPK 24                            // max KEPT edges per row per hop (lambda ~3.35)
#define ROW_STRIDE (N_HOPS * EMB)          // 192 floats per node in output

#define BUILD_THREADS (NNZ / 4)            // 500,000 threads, 4 edges each
#define BUILD_BLOCKS ((BUILD_THREADS + 255) / 256)
#define HOP_BLOCKS   ((N_NODES * 16) / 256)

// Per-hop compact kept-edge lists: {v (f32 bits), col} per record.
// +4 records of tail padding: the 4-wide unconditional loop may read up to
// 2 records past the last row's CAPK slots.
__device__ int2     g_edge[N_HOPS][(size_t)N_NODES * CAPK + 4];  // ~3 * 57.6 MB
__device__ uint32_t g_pcnt[N_NODES];       // 3 packed 10-bit per-hop counters

__host__ __device__ __forceinline__ uint32_t rotl32(uint32_t x, int r) {
    return (x << r) | (x >> (32 - r));
}

// Threefry-2x32, 20 rounds, exactly as jax._src.prng.threefry2x32.
__host__ __device__ __forceinline__ void threefry2x32(
    uint32_t k0, uint32_t k1, uint32_t c0, uint32_t c1,
    uint32_t& o0, uint32_t& o1)
{
    uint32_t ks2 = k0 ^ k1 ^ 0x1BD11BDAu;
    uint32_t x0 = c0 + k0;
    uint32_t x1 = c1 + k1;
#define TF_ROUND(r) { x0 += x1; x1 = rotl32(x1, (r)); x1 ^= x0; }
    TF_ROUND(13) TF_ROUND(15) TF_ROUND(26) TF_ROUND(6)
    x0 += k1;  x1 += ks2 + 1u;
    TF_ROUND(17) TF_ROUND(29) TF_ROUND(16) TF_ROUND(24)
    x0 += ks2; x1 += k0 + 2u;
    TF_ROUND(13) TF_ROUND(15) TF_ROUND(26) TF_ROUND(6)
    x0 += k0;  x1 += k1 + 3u;
    TF_ROUND(17) TF_ROUND(29) TF_ROUND(16) TF_ROUND(24)
    x0 += k1;  x1 += ks2 + 4u;
    TF_ROUND(13) TF_ROUND(15) TF_ROUND(26) TF_ROUND(6)
    x0 += ks2; x1 += k0 + 5u;
#undef TF_ROUND
    o0 = x0;
    o1 = x1;
}

// jax threefry_partitionable=True, bit_width=32:
// bits[i] = w0 ^ w1 of threefry(key, (hi32(i)=0, lo32(i)=i))
__device__ __forceinline__ uint32_t tf_bits32(uint32_t k0, uint32_t k1, uint32_t i) {
    uint32_t o0, o1;
    threefry2x32(k0, k1, 0u, i, o0, o1);
    return o0 ^ o1;
}

// Build per-hop compact kept-edge lists; 4 edges per thread for MLP on the
// atomic/scatter path, one atomic per edge (3 packed 10-bit counters).
// edge keep = floor(0.5 + u) > 0  <=>  u >= 0.5  <=>  top bit of bits set.
__global__ void __launch_bounds__(256)
build_kernel(const float* __restrict__ vals,
             const int* __restrict__ rows,
             const int* __restrict__ cols,
             uint32_t e0k0, uint32_t e0k1,
             uint32_t e1k0, uint32_t e1k1,
             uint32_t e2k0, uint32_t e2k1)
{
    unsigned t = blockIdx.x * 256u + threadIdx.x;
    if (t >= BUILD_THREADS) return;
    unsigned e4 = t * 4u;

    float4 v4 = __ldg(((const float4*)vals) + t);
    int4   r4 = __ldg(((const int4*)rows) + t);
    int4   c4 = __ldg(((const int4*)cols) + t);

    float va[4] = {v4.x, v4.y, v4.z, v4.w};
    int   ra[4] = {r4.x, r4.y, r4.z, r4.w};
    int   ca[4] = {c4.x, c4.y, c4.z, c4.w};

    // 12 independent threefry evals (high ILP), then 4 independent atomics.
    uint32_t k0a[4], k1a[4], k2a[4];
#pragma unroll
    for (int k = 0; k < 4; k++) {
        unsigned e = e4 + (unsigned)k;
        k0a[k] = tf_bits32(e0k0, e0k1, e) >> 31;
        k1a[k] = tf_bits32(e1k0, e1k1, e) >> 31;
        k2a[k] = tf_bits32(e2k0, e2k1, e) >> 31;
    }

#pragma unroll
    for (int k = 0; k < 4; k++) {
        uint32_t add = k0a[k] | (k1a[k] << 10) | (k2a[k] << 20);
        if (add == 0) continue;
        int r = ra[k];
        int2 rec = make_int2(__float_as_int(va[k] * 2.0f), ca[k]);
        uint32_t old = atomicAdd(&g_pcnt[r], add);
        if (k0a[k]) {
            uint32_t s = old & 0x3FFu;
            if (s < CAPK) g_edge[0][(size_t)r * CAPK + s] = rec;
        }
        if (k1a[k]) {
            uint32_t s = (old >> 10) & 0x3FFu;
            if (s < CAPK) g_edge[1][(size_t)r * CAPK + s] = rec;
        }
        if (k2a[k]) {
            uint32_t s = (old >> 20) & 0x3FFu;
            if (s < CAPK) g_edge[2][(size_t)r * CAPK + s] = rec;
        }
    }
}

// Fused SpMM + message dropout, one half-warp (16 lanes) per output row.
// Fully speculative, branch-light: record loads and gathers are issued
// unconditionally (stale/zero records hold valid finite data and in-range
// node ids, the run is deterministic), and out-of-degree contributions are
// cancelled by selecting v=0. The mdrop threefry executes while the head
// loads are in flight.
// mdrop keep = u >= 0.1f  <=>  bits >= (0xCCCCD << 9) = 0x19999A00
template <int HOP>
__global__ void __launch_bounds__(256)
hop_kernel(const float* __restrict__ user_e,
           const float* __restrict__ item_e,
           float* __restrict__ out,
           uint32_t mk0, uint32_t mk1)
{
    unsigned t = blockIdx.x * 256u + threadIdx.x;
    unsigned r = t >> 4;                  // row = half-warp id
    int hl = t & 15;

    const int2* ebase = g_edge[HOP] + (size_t)r * CAPK;
    const float* src_base = out + (size_t)(HOP - 1) * EMB;   // used for HOP>0

    auto src_row = [&](int c) -> const float4* {
        if (HOP == 0) {
            return (c < N_USERS)
                ? (const float4*)(user_e + (size_t)c * EMB)
                : (const float4*)(item_e + (size_t)(c - N_USERS) * EMB);
        } else {
            return (const float4*)(src_base + (size_t)c * ROW_STRIDE);
        }
    };

    // --- issue phase: independent load traffic; pcnt first (tail loop gate) ---
    uint32_t pc = g_pcnt[r];
    int2 rec0 = __ldg(&ebase[0]);          // speculative
    int2 rec1 = __ldg(&ebase[1]);          // speculative
    float4 s0 = __ldg(src_row(rec0.y) + hl);   // speculative gather
    float4 s1 = __ldg(src_row(rec1.y) + hl);   // speculative gather

    // --- threefry while loads are in flight (fully independent ALU) ---
    const float MSCALE = (float)(1.0 / (1.0 - 0.1));
    uint32_t f = r * 64u + (uint32_t)hl * 4u;
    uint32_t b0 = tf_bits32(mk0, mk1, f + 0u);
    uint32_t b1 = tf_bits32(mk0, mk1, f + 1u);
    uint32_t b2 = tf_bits32(mk0, mk1, f + 2u);
    uint32_t b3 = tf_bits32(mk0, mk1, f + 3u);
    float m0 = (b0 >= 0x19999A00u) ? MSCALE : 0.0f;
    float m1 = (b1 >= 0x19999A00u) ? MSCALE : 0.0f;
    float m2 = (b2 >= 0x19999A00u) ? MSCALE : 0.0f;
    float m3 = (b3 >= 0x19999A00u) ? MSCALE : 0.0f;

    int deg = min((int)((pc >> (10 * HOP)) & 0x3FFu), CAPK);

    // --- branchless accumulation of the speculative head ---
    float v0h = (deg > 0) ? __int_as_float(rec0.x) : 0.0f;
    float v1h = (deg > 1) ? __int_as_float(rec1.x) : 0.0f;
    float4 a0, a1;
    a0.x = v0h * s0.x; a0.y = v0h * s0.y; a0.z = v0h * s0.z; a0.w = v0h * s0.w;
    a1.x = v1h * s1.x; a1.y = v1h * s1.y; a1.z = v1h * s1.z; a1.w = v1h * s1.w;

    // --- remaining edges: 4-wide unconditional loads + gathers, MLP=4 ---
    for (int j = 2; j < deg; j += 4) {
        int2 r0 = __ldg(&ebase[j + 0]);
        int2 r1 = __ldg(&ebase[j + 1]);
        int2 r2 = __ldg(&ebase[j + 2]);
        int2 r3 = __ldg(&ebase[j + 3]);
        float4 t0 = __ldg(src_row(r0.y) + hl);
        float4 t1 = __ldg(src_row(r1.y) + hl);
        float4 t2 = __ldg(src_row(r2.y) + hl);
        float4 t3 = __ldg(src_row(r3.y) + hl);
        float v0 = (j + 0 < deg) ? __int_as_float(r0.x) : 0.0f;
        float v1 = (j + 1 < deg) ? __int_as_float(r1.x) : 0.0f;
        float v2 = (j + 2 < deg) ? __int_as_float(r2.x) : 0.0f;
        float v3 = (j + 3 < deg) ? __int_as_float(r3.x) : 0.0f;
        a0.x += v0 * t0.x; a0.y += v0 * t0.y; a0.z += v0 * t0.z; a0.w += v0 * t0.w;
        a1.x += v1 * t1.x; a1.y += v1 * t1.y; a1.z += v1 * t1.z; a1.w += v1 * t1.w;
        a0.x += v2 * t2.x; a0.y += v2 * t2.y; a0.z += v2 * t2.z; a0.w += v2 * t2.w;
        a1.x += v3 * t3.x; a1.y += v3 * t3.y; a1.z += v3 * t3.z; a1.w += v3 * t3.w;
    }

    float4 acc;
    acc.x = (a0.x + a1.x) * m0;
    acc.y = (a0.y + a1.y) * m1;
    acc.z = (a0.z + a1.z) * m2;
    acc.w = (a0.w + a1.w) * m3;

    float4* dst = (float4*)(out + (size_t)r * ROW_STRIDE + (size_t)HOP * EMB) + hl;
    *dst = acc;
}

extern "C" void kernel_launch(void* const* d_in, const int* in_sizes, int n_in,
                              void* d_out, int out_size)
{
    const float* user_e = (const float*)d_in[0];
    const float* item_e = (const float*)d_in[1];
    const float* vals   = (const float*)d_in[2];
    const int*   rows   = (const int*)d_in[3];
    const int*   cols   = (const int*)d_in[4];
    float* out = (float*)d_out;

    // drop_key = jax.random.key(42) -> (0, 42); subkey_h = threefry(key, (0, h_data))
    uint32_t ek[3][2], mk[3][2];
    for (int h = 0; h < 3; h++) {
        threefry2x32(0u, 42u, 0u, (uint32_t)(2 * h),     ek[h][0], ek[h][1]);
        threefry2x32(0u, 42u, 0u, (uint32_t)(2 * h + 1), mk[h][0], mk[h][1]);
    }

    // Zero the packed per-row counters (graph-capturable, no allocation)
    void* cnt_ptr = nullptr;
    cudaGetSymbolAddress(&cnt_ptr, g_pcnt);
    cudaMemsetAsync(cnt_ptr, 0, sizeof(uint32_t) * N_NODES, 0);

    build_kernel<<<BUILD_BLOCKS, 256>>>(
        vals, rows, cols,
        ek[0][0], ek[0][1], ek[1][0], ek[1][1], ek[2][0], ek[2][1]);

    hop_kernel<0><<<HOP_BLOCKS, 256>>>(user_e, item_e, out, mk[0][0], mk[0][1]);
    hop_kernel<1><<<HOP_BLOCKS, 256>>>(user_e, item_e, out, mk[1][0], mk[1][1]);
    hop_kernel<2><<<HOP_BLOCKS, 256>>>(user_e, item_e, out, mk[2][0], mk[2][1]);
}

// round 11
// speedup vs baseline: 1.0166x; 1.0166x over previous
#include <cuda_runtime.h>
#include <cstdint>

#define N_USERS 100000
#define N_ITEMS 200000
#define N_NODES (N_USERS + N_ITEMS)
#define EMB 64
#define N_HOPS 3
#define NNZ 2000000
#define CAPK 24                            // max KEPT edges per row per hop (lambda ~3.35)
#define ROW_STRIDE (N_HOPS * EMB)          // 192 floats per node in output

#define BUILD_THREADS (NNZ / 4)            // 500,000 threads, 4 edges each
#define BUILD_BLOCKS ((BUILD_THREADS + 255) / 256)
#define HOP_BLOCKS   ((N_NODES * 16) / 256)

// Per-hop compact kept-edge lists: {v (f32 bits), col} per record.
// +8 records of tail padding: the unconditional head/loop reads may touch up
// to slot deg+2 (<= CAPK+2) past the LAST row's list.
__device__ int2     g_edge[N_HOPS][(size_t)N_NODES * CAPK + 8];  // ~3 * 57.6 MB
__device__ uint32_t g_pcnt[N_NODES];       // 3 packed 10-bit per-hop counters

__host__ __device__ __forceinline__ uint32_t rotl32(uint32_t x, int r) {
    return (x << r) | (x >> (32 - r));
}

// Threefry-2x32, 20 rounds, exactly as jax._src.prng.threefry2x32.
__host__ __device__ __forceinline__ void threefry2x32(
    uint32_t k0, uint32_t k1, uint32_t c0, uint32_t c1,
    uint32_t& o0, uint32_t& o1)
{
    uint32_t ks2 = k0 ^ k1 ^ 0x1BD11BDAu;
    uint32_t x0 = c0 + k0;
    uint32_t x1 = c1 + k1;
#define TF_ROUND(r) { x0 += x1; x1 = rotl32(x1, (r)); x1 ^= x0; }
    TF_ROUND(13) TF_ROUND(15) TF_ROUND(26) TF_ROUND(6)
    x0 += k1;  x1 += ks2 + 1u;
    TF_ROUND(17) TF_ROUND(29) TF_ROUND(16) TF_ROUND(24)
    x0 += ks2; x1 += k0 + 2u;
    TF_ROUND(13) TF_ROUND(15) TF_ROUND(26) TF_ROUND(6)
    x0 += k0;  x1 += k1 + 3u;
    TF_ROUND(17) TF_ROUND(29) TF_ROUND(16) TF_ROUND(24)
    x0 += k1;  x1 += ks2 + 4u;
    TF_ROUND(13) TF_ROUND(15) TF_ROUND(26) TF_ROUND(6)
    x0 += ks2; x1 += k0 + 5u;
#undef TF_ROUND
    o0 = x0;
    o1 = x1;
}

// jax threefry_partitionable=True, bit_width=32:
// bits[i] = w0 ^ w1 of threefry(key, (hi32(i)=0, lo32(i)=i))
__device__ __forceinline__ uint32_t tf_bits32(uint32_t k0, uint32_t k1, uint32_t i) {
    uint32_t o0, o1;
    threefry2x32(k0, k1, 0u, i, o0, o1);
    return o0 ^ o1;
}

// Build per-hop compact kept-edge lists; 4 edges per thread for MLP on the
// atomic/scatter path, one atomic per edge (3 packed 10-bit counters).
// edge keep = floor(0.5 + u) > 0  <=>  u >= 0.5  <=>  top bit of bits set.
__global__ void __launch_bounds__(256)
build_kernel(const float* __restrict__ vals,
             const int* __restrict__ rows,
             const int* __restrict__ cols,
             uint32_t e0k0, uint32_t e0k1,
             uint32_t e1k0, uint32_t e1k1,
             uint32_t e2k0, uint32_t e2k1)
{
    unsigned t = blockIdx.x * 256u + threadIdx.x;
    if (t >= BUILD_THREADS) return;
    unsigned e4 = t * 4u;

    float4 v4 = __ldg(((const float4*)vals) + t);
    int4   r4 = __ldg(((const int4*)rows) + t);
    int4   c4 = __ldg(((const int4*)cols) + t);

    float va[4] = {v4.x, v4.y, v4.z, v4.w};
    int   ra[4] = {r4.x, r4.y, r4.z, r4.w};
    int   ca[4] = {c4.x, c4.y, c4.z, c4.w};

    // 12 independent threefry evals (high ILP), then 4 independent atomics.
    uint32_t k0a[4], k1a[4], k2a[4];
#pragma unroll
    for (int k = 0; k < 4; k++) {
        unsigned e = e4 + (unsigned)k;
        k0a[k] = tf_bits32(e0k0, e0k1, e) >> 31;
        k1a[k] = tf_bits32(e1k0, e1k1, e) >> 31;
        k2a[k] = tf_bits32(e2k0, e2k1, e) >> 31;
    }

#pragma unroll
    for (int k = 0; k < 4; k++) {
        uint32_t add = k0a[k] | (k1a[k] << 10) | (k2a[k] << 20);
        if (add == 0) continue;
        int r = ra[k];
        int2 rec = make_int2(__float_as_int(va[k] * 2.0f), ca[k]);
        uint32_t old = atomicAdd(&g_pcnt[r], add);
        if (k0a[k]) {
            uint32_t s = old & 0x3FFu;
            if (s < CAPK) g_edge[0][(size_t)r * CAPK + s] = rec;
        }
        if (k1a[k]) {
            uint32_t s = (old >> 10) & 0x3FFu;
            if (s < CAPK) g_edge[1][(size_t)r * CAPK + s] = rec;
        }
        if (k2a[k]) {
            uint32_t s = (old >> 20) & 0x3FFu;
            if (s < CAPK) g_edge[2][(size_t)r * CAPK + s] = rec;
        }
    }
}

// Fused SpMM + message dropout, one half-warp (16 lanes) per output row.
// Fully speculative head: records 0-3 (two int4 loads) AND their four gathers
// are issued unconditionally before anything waits (stale/zero records hold
// valid in-range node ids; out-of-degree contributions are cancelled by v=0).
// The mdrop threefry executes while those loads are in flight; the only
// dependent consumers are the final FFMAs.
// mdrop keep = u >= 0.1f  <=>  bits >= (0xCCCCD << 9) = 0x19999A00
template <int HOP>
__global__ void __launch_bounds__(256)
hop_kernel(const float* __restrict__ user_e,
           const float* __restrict__ item_e,
           float* __restrict__ out,
           uint32_t mk0, uint32_t mk1)
{
    unsigned t = blockIdx.x * 256u + threadIdx.x;
    unsigned r = t >> 4;                  // row = half-warp id
    int hl = t & 15;

    const int2* ebase = g_edge[HOP] + (size_t)r * CAPK;
    const float* src_base = out + (size_t)(HOP - 1) * EMB;   // used for HOP>0

    auto src_row = [&](int c) -> const float4* {
        if (HOP == 0) {
            return (c < N_USERS)
                ? (const float4*)(user_e + (size_t)c * EMB)
                : (const float4*)(item_e + (size_t)(c - N_USERS) * EMB);
        } else {
            return (const float4*)(src_base + (size_t)c * ROW_STRIDE);
        }
    };

    // --- issue phase: all independent load traffic, nothing waits ---
    uint32_t pc = g_pcnt[r];
    int4 p01 = __ldg((const int4*)(ebase + 0));    // records 0,1
    int4 p23 = __ldg((const int4*)(ebase + 2));    // records 2,3
    float4 s0 = __ldg(src_row(p01.y) + hl);        // speculative gathers
    float4 s1 = __ldg(src_row(p01.w) + hl);
    float4 s2 = __ldg(src_row(p23.y) + hl);
    float4 s3 = __ldg(src_row(p23.w) + hl);

    // --- threefry while loads are in flight (fully independent ALU) ---
    const float MSCALE = (float)(1.0 / (1.0 - 0.1));
    uint32_t f = r * 64u + (uint32_t)hl * 4u;
    uint32_t b0 = tf_bits32(mk0, mk1, f + 0u);
    uint32_t b1 = tf_bits32(mk0, mk1, f + 1u);
    uint32_t b2 = tf_bits32(mk0, mk1, f + 2u);
    uint32_t b3 = tf_bits32(mk0, mk1, f + 3u);
    float m0 = (b0 >= 0x19999A00u) ? MSCALE : 0.0f;
    float m1 = (b1 >= 0x19999A00u) ? MSCALE : 0.0f;
    float m2 = (b2 >= 0x19999A00u) ? MSCALE : 0.0f;
    float m3 = (b3 >= 0x19999A00u) ? MSCALE : 0.0f;

    int deg = min((int)((pc >> (10 * HOP)) & 0x3FFu), CAPK);

    // --- branchless accumulation of the speculative head (deg <= 4: done) ---
    float v0 = (deg > 0) ? __int_as_float(p01.x) : 0.0f;
    float v1 = (deg > 1) ? __int_as_float(p01.z) : 0.0f;
    float v2 = (deg > 2) ? __int_as_float(p23.x) : 0.0f;
    float v3 = (deg > 3) ? __int_as_float(p23.z) : 0.0f;
    float4 a0, a1;
    a0.x = v0 * s0.x; a0.y = v0 * s0.y; a0.z = v0 * s0.z; a0.w = v0 * s0.w;
    a1.x = v1 * s1.x; a1.y = v1 * s1.y; a1.z = v1 * s1.z; a1.w = v1 * s1.w;
    a0.x += v2 * s2.x; a0.y += v2 * s2.y; a0.z += v2 * s2.z; a0.w += v2 * s2.w;
    a1.x += v3 * s3.x; a1.y += v3 * s3.y; a1.z += v3 * s3.z; a1.w += v3 * s3.w;

    // --- remaining edges (~30% of rows): 4-wide unconditional, MLP=4 ---
    for (int j = 4; j < deg; j += 4) {
        int4 q01 = __ldg((const int4*)(ebase + j));
        int4 q23 = __ldg((const int4*)(ebase + j + 2));
        float4 t0 = __ldg(src_row(q01.y) + hl);
        float4 t1 = __ldg(src_row(q01.w) + hl);
        float4 t2 = __ldg(src_row(q23.y) + hl);
        float4 t3 = __ldg(src_row(q23.w) + hl);
        float w0 = (j + 0 < deg) ? __int_as_float(q01.x) : 0.0f;
        float w1 = (j + 1 < deg) ? __int_as_float(q01.z) : 0.0f;
        float w2 = (j + 2 < deg) ? __int_as_float(q23.x) : 0.0f;
        float w3 = (j + 3 < deg) ? __int_as_float(q23.z) : 0.0f;
        a0.x += w0 * t0.x; a0.y += w0 * t0.y; a0.z += w0 * t0.z; a0.w += w0 * t0.w;
        a1.x += w1 * t1.x; a1.y += w1 * t1.y; a1.z += w1 * t1.z; a1.w += w1 * t1.w;
        a0.x += w2 * t2.x; a0.y += w2 * t2.y; a0.z += w2 * t2.z; a0.w += w2 * t2.w;
        a1.x += w3 * t3.x; a1.y += w3 * t3.y; a1.z += w3 * t3.z; a1.w += w3 * t3.w;
    }

    float4 acc;
    acc.x = (a0.x + a1.x) * m0;
    acc.y = (a0.y + a1.y) * m1;
    acc.z = (a0.z + a1.z) * m2;
    acc.w = (a0.w + a1.w) * m3;

    float4* dst = (float4*)(out + (size_t)r * ROW_STRIDE + (size_t)HOP * EMB) + hl;
    *dst = acc;
}

extern "C" void kernel_launch(void* const* d_in, const int* in_sizes, int n_in,
                              void* d_out, int out_size)
{
    const float* user_e = (const float*)d_in[0];
    const float* item_e = (const float*)d_in[1];
    const float* vals   = (const float*)d_in[2];
    const int*   rows   = (const int*)d_in[3];
    const int*   cols   = (const int*)d_in[4];
    float* out = (float*)d_out;

    // drop_key = jax.random.key(42) -> (0, 42); subkey_h = threefry(key, (0, h_data))
    uint32_t ek[3][2], mk[3][2];
    for (int h = 0; h < 3; h++) {
        threefry2x32(0u, 42u, 0u, (uint32_t)(2 * h),     ek[h][0], ek[h][1]);
        threefry2x32(0u, 42u, 0u, (uint32_t)(2 * h + 1), mk[h][0], mk[h][1]);
    }

    // Zero the packed per-row counters (graph-capturable, no allocation)
    void* cnt_ptr = nullptr;
    cudaGetSymbolAddress(&cnt_ptr, g_pcnt);
    cudaMemsetAsync(cnt_ptr, 0, sizeof(uint32_t) * N_NODES, 0);

    build_kernel<<<BUILD_BLOCKS, 256>>>(
        vals, rows, cols,
        ek[0][0], ek[0][1], ek[1][0], ek[1][1], ek[2][0], ek[2][1]);

    hop_kernel<0><<<HOP_BLOCKS, 256>>>(user_e, item_e, out, mk[0][0], mk[0][1]);
    hop_kernel<1><<<HOP_BLOCKS, 256>>>(user_e, item_e, out, mk[1][0], mk[1][1]);
    hop_kernel<2><<<HOP_BLOCKS, 256>>>(user_e, item_e, out, mk[2][0], mk[2][1]);
}

// round 12
// speedup vs baseline: 1.0740x; 1.0564x over previous
#include <cuda_runtime.h>
#include <cstdint>

#define N_USERS 100000
#define N_ITEMS 200000
#define N_NODES (N_USERS + N_ITEMS)
#define EMB 64
#define N_HOPS 3
#define NNZ 2000000
#define CAPK 24                            // max KEPT edges per row per hop (lambda ~3.35)
#define ROW_STRIDE (N_HOPS * EMB)          // 192 floats per node in output

#define BUILD_THREADS (NNZ / 4)            // 500,000 threads, 4 edges each
#define BUILD_BLOCKS ((BUILD_THREADS + 255) / 256)
#define HOP_BLOCKS   ((N_NODES * 16) / 256)

// Per-hop compact kept-edge lists: {v (f32 bits), col} per record.
// +8 records of tail padding: the unconditional head/loop reads may touch up
// to slot deg+2 (<= CAPK+2) past the LAST row's list.
__device__ int2     g_edge[N_HOPS][(size_t)N_NODES * CAPK + 8];  // ~3 * 57.6 MB
__device__ uint32_t g_pcnt[N_NODES];       // 3 packed 10-bit per-hop counters

__host__ __device__ __forceinline__ uint32_t rotl32(uint32_t x, int r) {
    return (x << r) | (x >> (32 - r));
}

// Integer add forced onto the FMA pipe (IMAD) to offload the saturated ALU
// pipe (SHF/LOP3 live there and are irreducible).
__device__ __forceinline__ uint32_t addf(uint32_t a, uint32_t b) {
    uint32_t r;
    asm("mad.lo.u32 %0, %1, 0x1, %2;" : "=r"(r) : "r"(a), "r"(b));
    return r;
}

#ifdef __CUDA_ARCH__
#define TFADD(a, b) addf((a), (b))
#else
#define TFADD(a, b) ((a) + (b))
#endif

// Threefry-2x32, 20 rounds, exactly as jax._src.prng.threefry2x32.
__host__ __device__ __forceinline__ void threefry2x32(
    uint32_t k0, uint32_t k1, uint32_t c0, uint32_t c1,
    uint32_t& o0, uint32_t& o1)
{
    uint32_t ks2 = k0 ^ k1 ^ 0x1BD11BDAu;
    uint32_t x0 = TFADD(c0, k0);
    uint32_t x1 = TFADD(c1, k1);
#define TF_ROUND(r) { x0 = TFADD(x0, x1); x1 = rotl32(x1, (r)); x1 ^= x0; }
    TF_ROUND(13) TF_ROUND(15) TF_ROUND(26) TF_ROUND(6)
    x0 = TFADD(x0, k1);  x1 = TFADD(x1, ks2 + 1u);
    TF_ROUND(17) TF_ROUND(29) TF_ROUND(16) TF_ROUND(24)
    x0 = TFADD(x0, ks2); x1 = TFADD(x1, k0 + 2u);
    TF_ROUND(13) TF_ROUND(15) TF_ROUND(26) TF_ROUND(6)
    x0 = TFADD(x0, k0);  x1 = TFADD(x1, k1 + 3u);
    TF_ROUND(17) TF_ROUND(29) TF_ROUND(16) TF_ROUND(24)
    x0 = TFADD(x0, k1);  x1 = TFADD(x1, ks2 + 4u);
    TF_ROUND(13) TF_ROUND(15) TF_ROUND(26) TF_ROUND(6)
    x0 = TFADD(x0, ks2); x1 = TFADD(x1, k0 + 5u);
#undef TF_ROUND
    o0 = x0;
    o1 = x1;
}

// jax threefry_partitionable=True, bit_width=32:
// bits[i] = w0 ^ w1 of threefry(key, (hi32(i)=0, lo32(i)=i))
__device__ __forceinline__ uint32_t tf_bits32(uint32_t k0, uint32_t k1, uint32_t i) {
    uint32_t o0, o1;
    threefry2x32(k0, k1, 0u, i, o0, o1);
    return o0 ^ o1;
}

// Build per-hop compact kept-edge lists; 4 edges per thread for MLP on the
// atomic/scatter path, one atomic per edge (3 packed 10-bit counters).
// edge keep = floor(0.5 + u) > 0  <=>  u >= 0.5  <=>  top bit of bits set.
__global__ void __launch_bounds__(256)
build_kernel(const float* __restrict__ vals,
             const int* __restrict__ rows,
             const int* __restrict__ cols,
             uint32_t e0k0, uint32_t e0k1,
             uint32_t e1k0, uint32_t e1k1,
             uint32_t e2k0, uint32_t e2k1)
{
    unsigned t = blockIdx.x * 256u + threadIdx.x;
    if (t >= BUILD_THREADS) return;
    unsigned e4 = t * 4u;

    float4 v4 = __ldg(((const float4*)vals) + t);
    int4   r4 = __ldg(((const int4*)rows) + t);
    int4   c4 = __ldg(((const int4*)cols) + t);

    float va[4] = {v4.x, v4.y, v4.z, v4.w};
    int   ra[4] = {r4.x, r4.y, r4.z, r4.w};
    int   ca[4] = {c4.x, c4.y, c4.z, c4.w};

    // 12 independent threefry evals (high ILP), then 4 independent atomics.
    uint32_t k0a[4], k1a[4], k2a[4];
#pragma unroll
    for (int k = 0; k < 4; k++) {
        unsigned e = e4 + (unsigned)k;
        k0a[k] = tf_bits32(e0k0, e0k1, e) >> 31;
        k1a[k] = tf_bits32(e1k0, e1k1, e) >> 31;
        k2a[k] = tf_bits32(e2k0, e2k1, e) >> 31;
    }

#pragma unroll
    for (int k = 0; k < 4; k++) {
        uint32_t add = k0a[k] | (k1a[k] << 10) | (k2a[k] << 20);
        if (add == 0) continue;
        int r = ra[k];
        int2 rec = make_int2(__float_as_int(va[k] * 2.0f), ca[k]);
        uint32_t old = atomicAdd(&g_pcnt[r], add);
        if (k0a[k]) {
            uint32_t s = old & 0x3FFu;
            if (s < CAPK) g_edge[0][(size_t)r * CAPK + s] = rec;
        }
        if (k1a[k]) {
            uint32_t s = (old >> 10) & 0x3FFu;
            if (s < CAPK) g_edge[1][(size_t)r * CAPK + s] = rec;
        }
        if (k2a[k]) {
            uint32_t s = (old >> 20) & 0x3FFu;
            if (s < CAPK) g_edge[2][(size_t)r * CAPK + s] = rec;
        }
    }
}

// Fused SpMM + message dropout, one half-warp (16 lanes) per output row.
// Fully speculative head: records 0-3 (two int4 loads) AND their four gathers
// are issued unconditionally before anything waits (stale/zero records hold
// valid in-range node ids; out-of-degree contributions are cancelled by v=0).
// The mdrop threefry executes while those loads are in flight; the only
// dependent consumers are the final FFMAs.
// mdrop keep = u >= 0.1f  <=>  bits >= (0xCCCCD << 9) = 0x19999A00
template <int HOP>
__global__ void __launch_bounds__(256)
hop_kernel(const float* __restrict__ user_e,
           const float* __restrict__ item_e,
           float* __restrict__ out,
           uint32_t mk0, uint32_t mk1)
{
    unsigned t = blockIdx.x * 256u + threadIdx.x;
    unsigned r = t >> 4;                  // row = half-warp id
    int hl = t & 15;

    const int2* ebase = g_edge[HOP] + (size_t)r * CAPK;
    const float* src_base = out + (size_t)(HOP - 1) * EMB;   // used for HOP>0

    auto src_row = [&](int c) -> const float4* {
        if (HOP == 0) {
            return (c < N_USERS)
                ? (const float4*)(user_e + (size_t)c * EMB)
                : (const float4*)(item_e + (size_t)(c - N_USERS) * EMB);
        } else {
            return (const float4*)(src_base + (size_t)c * ROW_STRIDE);
        }
    };

    // --- issue phase: all independent load traffic, nothing waits ---
    uint32_t pc = g_pcnt[r];
    int4 p01 = __ldg((const int4*)(ebase + 0));    // records 0,1
    int4 p23 = __ldg((const int4*)(ebase + 2));    // records 2,3
    float4 s0 = __ldg(src_row(p01.y) + hl);        // speculative gathers
    float4 s1 = __ldg(src_row(p01.w) + hl);
    float4 s2 = __ldg(src_row(p23.y) + hl);
    float4 s3 = __ldg(src_row(p23.w) + hl);

    // --- threefry while loads are in flight (fully independent ALU) ---
    const float MSCALE = (float)(1.0 / (1.0 - 0.1));
    uint32_t f = r * 64u + (uint32_t)hl * 4u;
    uint32_t b0 = tf_bits32(mk0, mk1, f + 0u);
    uint32_t b1 = tf_bits32(mk0, mk1, f + 1u);
    uint32_t b2 = tf_bits32(mk0, mk1, f + 2u);
    uint32_t b3 = tf_bits32(mk0, mk1, f + 3u);
    float m0 = (b0 >= 0x19999A00u) ? MSCALE : 0.0f;
    float m1 = (b1 >= 0x19999A00u) ? MSCALE : 0.0f;
    float m2 = (b2 >= 0x19999A00u) ? MSCALE : 0.0f;
    float m3 = (b3 >= 0x19999A00u) ? MSCALE : 0.0f;

    int deg = min((int)((pc >> (10 * HOP)) & 0x3FFu), CAPK);

    // --- branchless accumulation of the speculative head (deg <= 4: done) ---
    float v0 = (deg > 0) ? __int_as_float(p01.x) : 0.0f;
    float v1 = (deg > 1) ? __int_as_float(p01.z) : 0.0f;
    float v2 = (deg > 2) ? __int_as_float(p23.x) : 0.0f;
    float v3 = (deg > 3) ? __int_as_float(p23.z) : 0.0f;
    float4 a0, a1;
    a0.x = v0 * s0.x; a0.y = v0 * s0.y; a0.z = v0 * s0.z; a0.w = v0 * s0.w;
    a1.x = v1 * s1.x; a1.y = v1 * s1.y; a1.z = v1 * s1.z; a1.w = v1 * s1.w;
    a0.x += v2 * s2.x; a0.y += v2 * s2.y; a0.z += v2 * s2.z; a0.w += v2 * s2.w;
    a1.x += v3 * s3.x; a1.y += v3 * s3.y; a1.z += v3 * s3.z; a1.w += v3 * s3.w;

    // --- remaining edges (~30% of rows): 4-wide unconditional, MLP=4 ---
    for (int j = 4; j < deg; j += 4) {
        int4 q01 = __ldg((const int4*)(ebase + j));
        int4 q23 = __ldg((const int4*)(ebase + j + 2));
        float4 t0 = __ldg(src_row(q01.y) + hl);
        float4 t1 = __ldg(src_row(q01.w) + hl);
        float4 t2 = __ldg(src_row(q23.y) + hl);
        float4 t3 = __ldg(src_row(q23.w) + hl);
        float w0 = (j + 0 < deg) ? __int_as_float(q01.x) : 0.0f;
        float w1 = (j + 1 < deg) ? __int_as_float(q01.z) : 0.0f;
        float w2 = (j + 2 < deg) ? __int_as_float(q23.x) : 0.0f;
        float w3 = (j + 3 < deg) ? __int_as_float(q23.z) : 0.0f;
        a0.x += w0 * t0.x; a0.y += w0 * t0.y; a0.z += w0 * t0.z; a0.w += w0 * t0.w;
        a1.x += w1 * t1.x; a1.y += w1 * t1.y; a1.z += w1 * t1.z; a1.w += w1 * t1.w;
        a0.x += w2 * t2.x; a0.y += w2 * t2.y; a0.z += w2 * t2.z; a0.w += w2 * t2.w;
        a1.x += w3 * t3.x; a1.y += w3 * t3.y; a1.z += w3 * t3.z; a1.w += w3 * t3.w;
    }

    float4 acc;
    acc.x = (a0.x + a1.x) * m0;
    acc.y = (a0.y + a1.y) * m1;
    acc.z = (a0.z + a1.z) * m2;
    acc.w = (a0.w + a1.w) * m3;

    float4* dst = (float4*)(out + (size_t)r * ROW_STRIDE + (size_t)HOP * EMB) + hl;
    *dst = acc;
}

extern "C" void kernel_launch(void* const* d_in, const int* in_sizes, int n_in,
                              void* d_out, int out_size)
{
    const float* user_e = (const float*)d_in[0];
    const float* item_e = (const float*)d_in[1];
    const float* vals   = (const float*)d_in[2];
    const int*   rows   = (const int*)d_in[3];
    const int*   cols   = (const int*)d_in[4];
    float* out = (float*)d_out;

    // drop_key = jax.random.key(42) -> (0, 42); subkey_h = threefry(key, (0, h_data))
    uint32_t ek[3][2], mk[3][2];
    for (int h = 0; h < 3; h++) {
        threefry2x32(0u, 42u, 0u, (uint32_t)(2 * h),     ek[h][0], ek[h][1]);
        threefry2x32(0u, 42u, 0u, (uint32_t)(2 * h + 1), mk[h][0], mk[h][1]);
    }

    // Zero the packed per-row counters (graph-capturable, no allocation)
    void* cnt_ptr = nullptr;
    cudaGetSymbolAddress(&cnt_ptr, g_pcnt);
    cudaMemsetAsync(cnt_ptr, 0, sizeof(uint32_t) * N_NODES, 0);

    build_kernel<<<BUILD_BLOCKS, 256>>>(
        vals, rows, cols,
        ek[0][0], ek[0][1], ek[1][0], ek[1][1], ek[2][0], ek[2][1]);

    hop_kernel<0><<<HOP_BLOCKS, 256>>>(user_e, item_e, out, mk[0][0], mk[0][1]);
    hop_kernel<1><<<HOP_BLOCKS, 256>>>(user_e, item_e, out, mk[1][0], mk[1][1]);
    hop_kernel<2><<<HOP_BLOCKS, 256>>>(user_e, item_e, out, mk[2][0], mk[2][1]);
}